// round 1
// baseline (speedup 1.0000x reference)
#include <cuda_runtime.h>
#include <math.h>

// Chamfer distance, N=M=16384, D=3.
// Strategy: d^2(i,j) = sq_a[i] + (sq_b[j] - 2*a.b[j]); precompute (-2b, sq_b),
// keep running min of t[j] = sq_b[j] - 2*a.b[j], add sq_a at the end.
// Inner loop uses packed fma.rn.f32x2 (2 j's per FFMA2): 3 FFMA2 + 2 FMNMX per
// (query, j-pair). Register-tile R=4 queries per thread to amortize LDS.

#define MAXN   16384
#define TPB    256
#define RQT    4
#define ICHUNK (TPB*RQT)   // 1024 queries per block-column
#define JCHUNK 512         // db points per block-row
#define JPAIRS (JCHUNK/2)  // 256 packed pairs (32B each -> 8KB smem)

typedef unsigned long long ull;

// packed db tables: per pair p of points (2p, 2p+1), 8 floats:
// [-2x0,-2x1, -2y0,-2y1, -2z0,-2z1, sq0,sq1]
__device__ float    g_pk1[MAXN * 4];
__device__ float    g_pk2[MAXN * 4];
__device__ unsigned g_min1[MAXN];   // min d^2 (clamped >=0) as ordered uint bits
__device__ unsigned g_min2[MAXN];

__device__ __forceinline__ ull dup2(float x) {
    unsigned u = __float_as_uint(x);
    return ((ull)u) | (((ull)u) << 32);
}
__device__ __forceinline__ ull fma2(ull a, ull b, ull c) {
    ull d;
    asm("fma.rn.f32x2 %0, %1, %2, %3;" : "=l"(d) : "l"(a), "l"(b), "l"(c));
    return d;
}
__device__ __forceinline__ float lo32(ull v) { return __uint_as_float((unsigned)v); }
__device__ __forceinline__ float hi32(ull v) { return __uint_as_float((unsigned)(v >> 32)); }

__global__ void prep_kernel(const float* __restrict__ p1, int n1,
                            const float* __restrict__ p2, int n2,
                            float* __restrict__ out) {
    int i = blockIdx.x * blockDim.x + threadIdx.x;
    if (i == 0) out[0] = 0.0f;
    if (i >= MAXN) return;
    int p = i >> 1, h = i & 1;
    const float INF = __uint_as_float(0x7F800000u);

    if (i < n1) {
        float x = p1[3*i], y = p1[3*i+1], z = p1[3*i+2];
        g_pk1[p*8 + 0 + h] = -2.0f * x;
        g_pk1[p*8 + 2 + h] = -2.0f * y;
        g_pk1[p*8 + 4 + h] = -2.0f * z;
        g_pk1[p*8 + 6 + h] = x*x + y*y + z*z;
    } else {
        g_pk1[p*8 + 0 + h] = 0.0f;
        g_pk1[p*8 + 2 + h] = 0.0f;
        g_pk1[p*8 + 4 + h] = 0.0f;
        g_pk1[p*8 + 6 + h] = INF;   // padding never wins the min
    }
    if (i < n2) {
        float x = p2[3*i], y = p2[3*i+1], z = p2[3*i+2];
        g_pk2[p*8 + 0 + h] = -2.0f * x;
        g_pk2[p*8 + 2 + h] = -2.0f * y;
        g_pk2[p*8 + 4 + h] = -2.0f * z;
        g_pk2[p*8 + 6 + h] = x*x + y*y + z*z;
    } else {
        g_pk2[p*8 + 0 + h] = 0.0f;
        g_pk2[p*8 + 2 + h] = 0.0f;
        g_pk2[p*8 + 4 + h] = 0.0f;
        g_pk2[p*8 + 6 + h] = INF;
    }
    g_min1[i] = 0x7F800000u;
    g_min2[i] = 0x7F800000u;
}

__global__ void __launch_bounds__(TPB)
chamfer_min(const float* __restrict__ p1, int n1,
            const float* __restrict__ p2, int n2) {
    const float*  q;
    const float4* db;
    unsigned*     gm;
    int nq;
    if (blockIdx.z == 0) { q = p1; nq = n1; db = (const float4*)g_pk2; gm = g_min1; }
    else                 { q = p2; nq = n2; db = (const float4*)g_pk1; gm = g_min2; }

    __shared__ float4 tile[JPAIRS * 2];   // 8 KB
    const float4* src = db + (size_t)blockIdx.y * (JPAIRS * 2);
    for (int k = threadIdx.x; k < JPAIRS * 2; k += TPB) tile[k] = src[k];

    int ibase = blockIdx.x * ICHUNK + threadIdx.x;

    ull  axx[RQT], ayy[RQT], azz[RQT];
    float sqa[RQT];
    bool  valid[RQT];
    #pragma unroll
    for (int r = 0; r < RQT; r++) {
        int i = ibase + r * TPB;
        float x = 0.f, y = 0.f, z = 0.f;
        valid[r] = (i < nq);
        if (valid[r]) { x = q[3*i]; y = q[3*i+1]; z = q[3*i+2]; }
        sqa[r] = x*x + y*y + z*z;
        axx[r] = dup2(x); ayy[r] = dup2(y); azz[r] = dup2(z);
    }
    __syncthreads();

    const float INF = __uint_as_float(0x7F800000u);
    float m0[RQT], m1[RQT];
    #pragma unroll
    for (int r = 0; r < RQT; r++) { m0[r] = INF; m1[r] = INF; }

    const ulonglong2* t2 = (const ulonglong2*)tile;
    #pragma unroll 2
    for (int p = 0; p < JPAIRS; p++) {
        ulonglong2 v0 = t2[2*p];       // v0.x=(bx0,bx1) v0.y=(by0,by1)
        ulonglong2 v1 = t2[2*p + 1];   // v1.x=(bz0,bz1) v1.y=(sq0,sq1)
        #pragma unroll
        for (int r = 0; r < RQT; r++) {
            ull t = fma2(axx[r], v0.x, fma2(ayy[r], v0.y, fma2(azz[r], v1.x, v1.y)));
            m0[r] = fminf(m0[r], lo32(t));
            m1[r] = fminf(m1[r], hi32(t));
        }
    }

    #pragma unroll
    for (int r = 0; r < RQT; r++) {
        if (!valid[r]) continue;
        float m  = fminf(m0[r], m1[r]);
        float d2 = fmaxf(m + sqa[r], 0.0f);   // clamp: now non-negative -> uint order == float order
        atomicMin(&gm[ibase + r * TPB], __float_as_uint(d2));
    }
}

__global__ void chamfer_reduce(float* __restrict__ out, int n1, int n2) {
    __shared__ float ssum[32];
    int i = blockIdx.x * blockDim.x + threadIdx.x;
    float d = 0.0f;
    if (i < n1) {
        d = sqrtf(__uint_as_float(g_min1[i]));
    } else {
        int j = i - n1;
        if (j < n2) d = sqrtf(__uint_as_float(g_min2[j]));
    }
    #pragma unroll
    for (int o = 16; o; o >>= 1) d += __shfl_down_sync(0xffffffffu, d, o);
    int lane = threadIdx.x & 31, w = threadIdx.x >> 5;
    if (lane == 0) ssum[w] = d;
    __syncthreads();
    if (w == 0) {
        float v = (lane < (int)(blockDim.x >> 5)) ? ssum[lane] : 0.0f;
        #pragma unroll
        for (int o = 16; o; o >>= 1) v += __shfl_down_sync(0xffffffffu, v, o);
        if (lane == 0) atomicAdd(out, v);
    }
}

extern "C" void kernel_launch(void* const* d_in, const int* in_sizes, int n_in,
                              void* d_out, int out_size) {
    const float* p1 = (const float*)d_in[0];
    const float* p2 = (const float*)d_in[1];
    int n1 = in_sizes[0] / 3;
    int n2 = in_sizes[1] / 3;
    float* out = (float*)d_out;

    prep_kernel<<<(MAXN + TPB - 1) / TPB, TPB>>>(p1, n1, p2, n2, out);

    int nmax    = n1 > n2 ? n1 : n2;
    int iblocks = (nmax + ICHUNK - 1) / ICHUNK;   // 16
    int jsplits = (nmax + JCHUNK - 1) / JCHUNK;   // 32
    dim3 grid(iblocks, jsplits, 2);               // 1024 blocks
    chamfer_min<<<grid, TPB>>>(p1, n1, p2, n2);

    int total = n1 + n2;
    chamfer_reduce<<<(total + 511) / 512, 512>>>(out, n1, n2);
}